// round 9
// baseline (speedup 1.0000x reference)
#include <cuda_runtime.h>

// BatteryRNNCell, R8: fused single kernel (R7 design) with the coherence bug
// fixed. R7 read the table via __ldg (LDG.E.CONSTANT, non-coherent path,
// exempt from acquire ordering) -> wave-1 readers saw stale zeros. Now the
// table read is a plain generic ld.global.v2.f32 (coherent, ordered after the
// acquire flag poll). Builders = blocks 0..15, one 256-entry segment each.

#define DEVI __device__ __forceinline__

#define R_CONST    8.3144621f
#define F_CONST    96487.0f
#define KN_C       20000.0f
#define VOL_C      2.2e-05f
#define VOLS_C     (0.1f * VOL_C)
#define VOLB_C     (VOL_C - VOLS_C)
#define U0P_C      4.03f
#define U0N_C      0.01f

#define TAB_N 4096
#define THREADS 256
#define N_SEG (TAB_N / THREADS)   // 16 builder blocks / flag segments

// Scratch: tab[i] = (f(x_i), f(x_{i+1}) - f(x_i)), x_i = i/TAB_N.
__device__ float2 g_mlp_tab[TAB_N];
__device__ int    g_done[N_SEG];   // zero at module load; idempotently set to 1

DEVI float fast_tanh(float x) {
    float e = __expf(2.0f * x);
    return 1.0f - __fdividef(2.0f, e + 1.0f);
}

DEVI float clampf(float v, float lo, float hi) {
    return fminf(fmaxf(v, lo), hi);
}

DEVI float mlp_eval(float x,
                    const float* __restrict__ Wp0, const float* __restrict__ bp0,
                    const float* __restrict__ Wp2, const float* __restrict__ bp2,
                    const float* __restrict__ Wp4, const float* __restrict__ bp4) {
    float h[8];
    #pragma unroll
    for (int j = 0; j < 8; j++)
        h[j] = fast_tanh(fmaf(__ldg(&Wp0[j]), x, __ldg(&bp0[j])));
    float out = __ldg(&bp4[0]);
    #pragma unroll
    for (int k = 0; k < 4; k++) {
        float a = __ldg(&bp2[k]);
        #pragma unroll
        for (int j = 0; j < 8; j++)
            a = fmaf(__ldg(&Wp2[k * 8 + j]), h[j], a);
        out = fmaf(__ldg(&Wp4[k]), fast_tanh(a), out);
    }
    return out;
}

__global__ void __launch_bounds__(THREADS) battery_cell_kernel(
    const float* __restrict__ inputs,
    const float* __restrict__ states,
    const float* __restrict__ qMax,
    const float* __restrict__ Ro,
    const float* __restrict__ Wp0, const float* __restrict__ bp0,
    const float* __restrict__ Wp2, const float* __restrict__ bp2,
    const float* __restrict__ Wp4, const float* __restrict__ bp4,
    const float* __restrict__ Wn,  const float* __restrict__ bn,
    float* __restrict__ outV, float* __restrict__ outX, int n)
{
    const int tid = threadIdx.x;
    const int bid = blockIdx.x;

    // ---- builder blocks: fill one 256-entry table segment, release its flag ----
    if (bid < N_SEG) {
        __shared__ float sf[THREADS + 1];
        const float inv = 1.0f / (float)TAB_N;
        int ti = bid * THREADS + tid;
        sf[tid] = mlp_eval((float)ti * inv, Wp0, bp0, Wp2, bp2, Wp4, bp4);
        if (tid == 0)
            sf[THREADS] = mlp_eval((float)(bid * THREADS + THREADS) * inv,
                                   Wp0, bp0, Wp2, bp2, Wp4, bp4);
        __syncthreads();
        g_mlp_tab[ti] = make_float2(sf[tid], sf[tid + 1] - sf[tid]);
        __threadfence();          // table writes visible device-wide
        __syncthreads();          // all builder threads' fences done
        if (tid == 0) {
            int one = 1;
            asm volatile("st.global.release.gpu.b32 [%0], %1;"
                         :: "l"(&g_done[bid]), "r"(one) : "memory");
        }
    }

    const int b = bid * THREADS + tid;
    if (b >= n) return;

    // ---- coalesced per-element loads ----
    const float4* st4 = reinterpret_cast<const float4*>(states);
    float4 s0 = st4[2 * b];       // Tb, Vo, Vsn, Vsp
    float4 s1 = st4[2 * b + 1];   // qnB, qnS, qpB, qpS
    float i   = inputs[b];
    float qM  = qMax[b];
    float ro  = Ro[b];

    float Tb = s0.x, Vo = s0.y, Vsn = s0.z, Vsp = s0.w;
    float qnB = s1.x, qnS = s1.y, qpB = s1.z, qpS = s1.w;

    float inv_qSMax = __fdividef(1.0f, qM * 1000.0f);

    // ---- getNextState ----
    float xpS = clampf(qpS * inv_qSMax, 1e-18f, 1.0f);
    float xnS = clampf(qnS * inv_qSMax, 1e-18f, 1.0f);
    float Jn0 = 1e-18f + KN_C * sqrtf(xnS - xnS * xnS);
    float Jp0 = 1e-18f + KN_C * sqrtf(xpS - xpS * xpS);

    const float cB = 1.0f / (VOLB_C * 7.0e6f);
    const float cS = 1.0f / (VOLS_C * 7.0e6f);
    float qdn = qnB * cB - qnS * cS;
    float qdp = qpB * cB - qpS * cS;

    float J = i * 5000.0f;

    float VoNom  = i * ro * 10.0f;
    const float C1 = R_CONST / F_CONST / 0.5f;
    float un = __fdividef(J, 2.0f * Jn0);
    float up = __fdividef(J, 2.0f * Jp0);
    float VsnNom = C1 * Tb * __logf(un + sqrtf(fmaf(un, un, 1.0f)));
    float VspNom = C1 * Tb * __logf(up + sqrtf(fmaf(up, up, 1.0f)));

    float Tb2  = Tb;
    float Vo2  = Vo  + (VoNom  - Vo ) * (1.0f / 10.0f);
    float Vsn2 = Vsn + (VsnNom - Vsn) * (1.0f / 90.0f);
    float Vsp2 = Vsp + (VspNom - Vsp) * (1.0f / 90.0f);
    float qnB2 = qnB - qdn;
    float qnS2 = qnS + qdn - i;
    float qpB2 = qpB - qdp;
    float qpS2 = qpS + i + qdp;

    // ---- table-independent output math + XNew stores ----
    float xpo = qpS2 * inv_qSMax;
    float xno = qnS2 * inv_qSMax;

    float VenMLP = fmaf(xno, __ldg(&Wn[0]), __ldg(&bn[0]));

    float ratio_p = clampf(__fdividef(1.0f - xpo, xpo), 1e-18f, 1e18f);
    float ratio_n = clampf(__fdividef(1.0f - xno, xno), 1e-18f, 1e18f);
    const float C2 = R_CONST / F_CONST;
    float Vep_part = U0P_C + C2 * Tb2 * __logf(ratio_p);   // + VepMLP later
    float Ven      = U0N_C + C2 * Tb2 * __logf(ratio_n) + VenMLP;

    float4* ox4 = reinterpret_cast<float4*>(outX);
    ox4[2 * b]     = make_float4(Tb2, Vo2, Vsn2, Vsp2);
    ox4[2 * b + 1] = make_float4(qnB2, qnS2, qpB2, qpS2);

    // ---- acquire-wait for the needed segment, then a COHERENT table read ----
    float t = xpo * (float)TAB_N;
    int idx = min(max(__float2int_rd(t), 0), TAB_N - 1);
    int seg = idx >> 8;

    int done;
    asm volatile("ld.global.acquire.gpu.b32 %0, [%1];"
                 : "=r"(done) : "l"(&g_done[seg]) : "memory");
    while (done == 0) {
        __nanosleep(100);
        asm volatile("ld.global.acquire.gpu.b32 %0, [%1];"
                     : "=r"(done) : "l"(&g_done[seg]) : "memory");
    }

    // Plain generic load (NOT __ldg/.nc): coherent, ordered after the acquire.
    float tv_f, tv_d;
    asm volatile("ld.global.v2.f32 {%0, %1}, [%2];"
                 : "=f"(tv_f), "=f"(tv_d) : "l"(&g_mlp_tab[idx]) : "memory");
    float VepMLP = fmaf(tv_d, t - (float)idx, tv_f);

    outV[b] = (Vep_part + VepMLP) - Ven - Vo2 - Vsn2 - Vsp2;
}

extern "C" void kernel_launch(void* const* d_in, const int* in_sizes, int n_in,
                              void* d_out, int out_size) {
    const float* inputs = (const float*)d_in[0];
    const float* states = (const float*)d_in[1];
    const float* qMax   = (const float*)d_in[2];
    const float* Ro     = (const float*)d_in[3];
    const float* Wp0    = (const float*)d_in[4];
    const float* bp0    = (const float*)d_in[5];
    const float* Wp2    = (const float*)d_in[6];
    const float* bp2    = (const float*)d_in[7];
    const float* Wp4    = (const float*)d_in[8];
    const float* bp4    = (const float*)d_in[9];
    const float* Wn     = (const float*)d_in[10];
    const float* bn     = (const float*)d_in[11];

    int n = in_sizes[0];  // B
    float* outV = (float*)d_out;
    float* outX = outV + n;

    int blocks = (n + THREADS - 1) / THREADS;
    if (blocks < N_SEG) blocks = N_SEG;   // builders must exist

    battery_cell_kernel<<<blocks, THREADS>>>(
        inputs, states, qMax, Ro, Wp0, bp0, Wp2, bp2, Wp4, bp4, Wn, bn,
        outV, outX, n);
}

// round 11
// speedup vs baseline: 1.2604x; 1.2604x over previous
#include <cuda_runtime.h>

// BatteryRNNCell, R10: fused single kernel, block-level gate.
// Builders (blocks 0..15) fill one 256-entry table segment each, threadfence,
// then release-add to a global counter. Every block does ALL table-independent
// work first (R4 code, unclobbered), then thread 0 alone acquire-polls the
// counter, __syncthreads, and only then do threads read the table (__ldg is
// safe: it cannot be hoisted across __syncthreads, and the block is ordered
// after the builders' release by thread0-acquire + barrier).

#define DEVI __device__ __forceinline__

#define R_CONST    8.3144621f
#define F_CONST    96487.0f
#define KN_C       20000.0f
#define VOL_C      2.2e-05f
#define VOLS_C     (0.1f * VOL_C)
#define VOLB_C     (VOL_C - VOLS_C)
#define U0P_C      4.03f
#define U0N_C      0.01f

#define TAB_N 4096
#define THREADS 256
#define N_SEG (TAB_N / THREADS)   // 16 builder blocks

// Scratch: tab[i] = (f(x_i), f(x_{i+1}) - f(x_i)), x_i = i/TAB_N.
__device__ float2 g_mlp_tab[TAB_N];
__device__ int    g_count;         // monotonically grows across replays

DEVI float fast_tanh(float x) {
    float e = __expf(2.0f * x);
    return 1.0f - __fdividef(2.0f, e + 1.0f);
}

DEVI float clampf(float v, float lo, float hi) {
    return fminf(fmaxf(v, lo), hi);
}

DEVI float mlp_eval(float x,
                    const float* __restrict__ Wp0, const float* __restrict__ bp0,
                    const float* __restrict__ Wp2, const float* __restrict__ bp2,
                    const float* __restrict__ Wp4, const float* __restrict__ bp4) {
    float h[8];
    #pragma unroll
    for (int j = 0; j < 8; j++)
        h[j] = fast_tanh(fmaf(__ldg(&Wp0[j]), x, __ldg(&bp0[j])));
    float out = __ldg(&bp4[0]);
    #pragma unroll
    for (int k = 0; k < 4; k++) {
        float a = __ldg(&bp2[k]);
        #pragma unroll
        for (int j = 0; j < 8; j++)
            a = fmaf(__ldg(&Wp2[k * 8 + j]), h[j], a);
        out = fmaf(__ldg(&Wp4[k]), fast_tanh(a), out);
    }
    return out;
}

__global__ void __launch_bounds__(THREADS) battery_cell_kernel(
    const float* __restrict__ inputs,
    const float* __restrict__ states,
    const float* __restrict__ qMax,
    const float* __restrict__ Ro,
    const float* __restrict__ Wp0, const float* __restrict__ bp0,
    const float* __restrict__ Wp2, const float* __restrict__ bp2,
    const float* __restrict__ Wp4, const float* __restrict__ bp4,
    const float* __restrict__ Wn,  const float* __restrict__ bn,
    float* __restrict__ outV, float* __restrict__ outX, int n)
{
    const int tid = threadIdx.x;
    const int bid = blockIdx.x;

    // ---- builder blocks: fill one table segment, then release-add counter ----
    if (bid < N_SEG) {
        __shared__ float sf[THREADS + 1];
        const float inv = 1.0f / (float)TAB_N;
        int ti = bid * THREADS + tid;
        sf[tid] = mlp_eval((float)ti * inv, Wp0, bp0, Wp2, bp2, Wp4, bp4);
        if (tid == 0)
            sf[THREADS] = mlp_eval((float)(bid * THREADS + THREADS) * inv,
                                   Wp0, bp0, Wp2, bp2, Wp4, bp4);
        __syncthreads();
        g_mlp_tab[ti] = make_float2(sf[tid], sf[tid + 1] - sf[tid]);
        __threadfence();          // table writes visible device-wide
        __syncthreads();          // all builder lanes' fences complete
        if (tid == 0)
            asm volatile("red.global.release.gpu.add.s32 [%0], 1;"
                         :: "l"(&g_count) : "memory");
    }

    const int b = bid * THREADS + tid;
    const bool valid = (b < n);

    float Vep_part = 0.0f, Ven = 0.0f, Vo2 = 0.0f, Vsn2 = 0.0f, Vsp2 = 0.0f;
    float t = 0.0f;
    int idx = 0;

    if (valid) {
        // ---- coalesced per-element loads ----
        const float4* st4 = reinterpret_cast<const float4*>(states);
        float4 s0 = st4[2 * b];       // Tb, Vo, Vsn, Vsp
        float4 s1 = st4[2 * b + 1];   // qnB, qnS, qpB, qpS
        float i   = inputs[b];
        float qM  = qMax[b];
        float ro  = Ro[b];

        float Tb = s0.x, Vo = s0.y, Vsn = s0.z, Vsp = s0.w;
        float qnB = s1.x, qnS = s1.y, qpB = s1.z, qpS = s1.w;

        float inv_qSMax = __fdividef(1.0f, qM * 1000.0f);

        // ---- getNextState ----
        float xpS = clampf(qpS * inv_qSMax, 1e-18f, 1.0f);
        float xnS = clampf(qnS * inv_qSMax, 1e-18f, 1.0f);
        float Jn0 = 1e-18f + KN_C * sqrtf(xnS - xnS * xnS);
        float Jp0 = 1e-18f + KN_C * sqrtf(xpS - xpS * xpS);

        const float cB = 1.0f / (VOLB_C * 7.0e6f);
        const float cS = 1.0f / (VOLS_C * 7.0e6f);
        float qdn = qnB * cB - qnS * cS;
        float qdp = qpB * cB - qpS * cS;

        float J = i * 5000.0f;

        float VoNom  = i * ro * 10.0f;
        const float C1 = R_CONST / F_CONST / 0.5f;
        float un = __fdividef(J, 2.0f * Jn0);
        float up = __fdividef(J, 2.0f * Jp0);
        float VsnNom = C1 * Tb * __logf(un + sqrtf(fmaf(un, un, 1.0f)));
        float VspNom = C1 * Tb * __logf(up + sqrtf(fmaf(up, up, 1.0f)));

        float Tb2  = Tb;
        Vo2  = Vo  + (VoNom  - Vo ) * (1.0f / 10.0f);
        Vsn2 = Vsn + (VsnNom - Vsn) * (1.0f / 90.0f);
        Vsp2 = Vsp + (VspNom - Vsp) * (1.0f / 90.0f);
        float qnB2 = qnB - qdn;
        float qnS2 = qnS + qdn - i;
        float qpB2 = qpB - qdp;
        float qpS2 = qpS + i + qdp;

        // ---- table-independent output math + XNew stores ----
        float xpo = qpS2 * inv_qSMax;
        float xno = qnS2 * inv_qSMax;

        float VenMLP = fmaf(xno, __ldg(&Wn[0]), __ldg(&bn[0]));

        float ratio_p = clampf(__fdividef(1.0f - xpo, xpo), 1e-18f, 1e18f);
        float ratio_n = clampf(__fdividef(1.0f - xno, xno), 1e-18f, 1e18f);
        const float C2 = R_CONST / F_CONST;
        Vep_part = U0P_C + C2 * Tb2 * __logf(ratio_p);   // + VepMLP later
        Ven      = U0N_C + C2 * Tb2 * __logf(ratio_n) + VenMLP;

        float4* ox4 = reinterpret_cast<float4*>(outX);
        ox4[2 * b]     = make_float4(Tb2, Vo2, Vsn2, Vsp2);
        ox4[2 * b + 1] = make_float4(qnB2, qnS2, qpB2, qpS2);

        t = xpo * (float)TAB_N;
        idx = min(max(__float2int_rd(t), 0), TAB_N - 1);
    }

    // ---- block-level gate: thread 0 acquires the counter, barrier fans out ----
    if (tid == 0) {
        int c;
        asm volatile("ld.global.acquire.gpu.b32 %0, [%1];"
                     : "=r"(c) : "l"(&g_count) : "memory");
        while (c < N_SEG) {
            __nanosleep(200);
            asm volatile("ld.global.acquire.gpu.b32 %0, [%1];"
                         : "=r"(c) : "l"(&g_count) : "memory");
        }
    }
    __syncthreads();   // orders the whole block after thread 0's acquire

    if (valid) {
        float2 tv = __ldg(&g_mlp_tab[idx]);   // cannot hoist across __syncthreads
        float VepMLP = fmaf(tv.y, t - (float)idx, tv.x);
        outV[b] = (Vep_part + VepMLP) - Ven - Vo2 - Vsn2 - Vsp2;
    }
}

extern "C" void kernel_launch(void* const* d_in, const int* in_sizes, int n_in,
                              void* d_out, int out_size) {
    const float* inputs = (const float*)d_in[0];
    const float* states = (const float*)d_in[1];
    const float* qMax   = (const float*)d_in[2];
    const float* Ro     = (const float*)d_in[3];
    const float* Wp0    = (const float*)d_in[4];
    const float* bp0    = (const float*)d_in[5];
    const float* Wp2    = (const float*)d_in[6];
    const float* bp2    = (const float*)d_in[7];
    const float* Wp4    = (const float*)d_in[8];
    const float* bp4    = (const float*)d_in[9];
    const float* Wn     = (const float*)d_in[10];
    const float* bn     = (const float*)d_in[11];

    int n = in_sizes[0];  // B
    float* outV = (float*)d_out;
    float* outX = outV + n;

    int blocks = (n + THREADS - 1) / THREADS;
    if (blocks < N_SEG) blocks = N_SEG;   // builders must exist

    battery_cell_kernel<<<blocks, THREADS>>>(
        inputs, states, qMax, Ro, Wp0, bp0, Wp2, bp2, Wp4, bp4, Wn, bn,
        outV, outX, n);
}